// round 1
// baseline (speedup 1.0000x reference)
#include <cuda_runtime.h>
#include <math_constants.h>

#define HD     1024
#define NHEADS 16
#define DHEAD  64
#define SEQ    2048
#define NB     2
#define ROWS   (NB * SEQ)   // 4096

// Scratch (allocation-free rule: __device__ globals)
__device__ float g_q[ROWS * HD];
__device__ float g_k[ROWS * HD];
__device__ float g_v[ROWS * HD];
__device__ float g_ctx[ROWS * HD];

// ---------------------------------------------------------------------------
// SGEMM body: C[M,N] = A[M,K] @ B[K,N], row-major. Tiles 128x128x16,
// 256 threads, 8x8 micro-tile. M,N,K assumed multiples of 128/128/16.
// ---------------------------------------------------------------------------
__device__ __forceinline__ void sgemm128(const float* __restrict__ A,
                                         const float* __restrict__ B,
                                         float* __restrict__ C,
                                         int K, int N)
{
    __shared__ float As[16][128];   // transposed: As[k][m]
    __shared__ float Bs[16][128];   // Bs[k][n]

    const int tid = threadIdx.x;
    const int tr  = tid >> 4;       // 0..15
    const int tc  = tid & 15;       // 0..15
    const int bm  = blockIdx.y << 7;
    const int bn  = blockIdx.x << 7;

    float acc[8][8];
#pragma unroll
    for (int i = 0; i < 8; i++)
#pragma unroll
        for (int j = 0; j < 8; j++) acc[i][j] = 0.0f;

    for (int kt = 0; kt < K; kt += 16) {
        __syncthreads();
#pragma unroll
        for (int it = 0; it < 2; it++) {
            int id = tid + it * 256;            // 0..511
            // A tile: 128 rows x 4 float4 = 512 float4
            int am_ = id >> 2, ac = id & 3;
            float4 av = *reinterpret_cast<const float4*>(&A[(bm + am_) * K + kt + ac * 4]);
            As[ac * 4 + 0][am_] = av.x;
            As[ac * 4 + 1][am_] = av.y;
            As[ac * 4 + 2][am_] = av.z;
            As[ac * 4 + 3][am_] = av.w;
            // B tile: 16 rows x 32 float4 = 512 float4
            int bk = id >> 5, bc = id & 31;
            float4 bv = *reinterpret_cast<const float4*>(&B[(kt + bk) * N + bn + bc * 4]);
            *reinterpret_cast<float4*>(&Bs[bk][bc * 4]) = bv;
        }
        __syncthreads();

#pragma unroll
        for (int kk = 0; kk < 16; kk++) {
            float a[8], b[8];
            *reinterpret_cast<float4*>(&a[0]) = *reinterpret_cast<const float4*>(&As[kk][tr * 8]);
            *reinterpret_cast<float4*>(&a[4]) = *reinterpret_cast<const float4*>(&As[kk][tr * 8 + 4]);
            *reinterpret_cast<float4*>(&b[0]) = *reinterpret_cast<const float4*>(&Bs[kk][tc * 8]);
            *reinterpret_cast<float4*>(&b[4]) = *reinterpret_cast<const float4*>(&Bs[kk][tc * 8 + 4]);
#pragma unroll
            for (int i = 0; i < 8; i++)
#pragma unroll
                for (int j = 0; j < 8; j++)
                    acc[i][j] += a[i] * b[j];
        }
    }

#pragma unroll
    for (int i = 0; i < 8; i++) {
#pragma unroll
        for (int j4 = 0; j4 < 2; j4++) {
            float4 v = make_float4(acc[i][j4 * 4 + 0], acc[i][j4 * 4 + 1],
                                   acc[i][j4 * 4 + 2], acc[i][j4 * 4 + 3]);
            *reinterpret_cast<float4*>(&C[(bm + tr * 8 + i) * N + bn + tc * 8 + j4 * 4]) = v;
        }
    }
}

// QKV fused: blockIdx.z selects which projection
__global__ __launch_bounds__(256, 2)
void qkv_gemm_kernel(const float* __restrict__ X,
                     const float* __restrict__ Wq,
                     const float* __restrict__ Wk,
                     const float* __restrict__ Wv)
{
    const float* W = (blockIdx.z == 0) ? Wq : (blockIdx.z == 1 ? Wk : Wv);
    float* O = (blockIdx.z == 0) ? g_q : (blockIdx.z == 1 ? g_k : g_v);
    sgemm128(X, W, O, HD, HD);
}

__global__ __launch_bounds__(256, 2)
void out_gemm_kernel(const float* __restrict__ Wo, float* __restrict__ Out)
{
    sgemm128(g_ctx, Wo, Out, HD, HD);
}

// ---------------------------------------------------------------------------
// Flash attention, fp32. Block handles (b, h, 64 query rows).
// BQ=64, BKV=32, d=64. 256 threads = 16x16.
// Faithful to reference: s = (q.k + FLT_LOWEST*max(fmask, 1-amq*amk)) / 32
// ---------------------------------------------------------------------------
__global__ __launch_bounds__(256)
void flash_kernel(const float* __restrict__ am)
{
    __shared__ float Qs[64][68];
    __shared__ float Ks[32][68];
    __shared__ float Vs[32][68];
    __shared__ float Ps[64][33];
    __shared__ float amks[32];

    const int tid = threadIdx.x;
    const int tr = tid >> 4;           // 0..15
    const int tc = tid & 15;           // 0..15
    const int r0 = tr * 4;             // query rows r0..r0+3 (of 64)
    const int c0 = tc * 2;             // S cols c0..c0+1 (of 32)
    const int n0 = tc * 4;             // O cols n0..n0+3 (of 64)

    const int qb = blockIdx.x;         // 0..31
    const int h  = blockIdx.y;
    const int b  = blockIdx.z;
    const int qbase = qb * 64;

    const long gbase = (long)b * SEQ * HD + h * DHEAD;

    // Load Q tile (64 x 64)
#pragma unroll
    for (int it = 0; it < 4; it++) {
        int id = tid + it * 256;       // 0..1023 float4s
        int r = id >> 4, c4 = id & 15;
        float4 v = *reinterpret_cast<const float4*>(&g_q[gbase + (long)(qbase + r) * HD + c4 * 4]);
        *reinterpret_cast<float4*>(&Qs[r][c4 * 4]) = v;
    }

    float amq[4];
#pragma unroll
    for (int i = 0; i < 4; i++)
        amq[i] = am[b * SEQ + qbase + r0 + i];

    float m_i[4], l_i[4], o[4][4];
#pragma unroll
    for (int i = 0; i < 4; i++) {
        m_i[i] = -CUDART_INF_F;
        l_i[i] = 0.0f;
#pragma unroll
        for (int j = 0; j < 4; j++) o[i][j] = 0.0f;
    }

    const int nkb = qb * 2 + 2;        // causal: kv blocks 0 .. nkb-1
    for (int kb = 0; kb < nkb; kb++) {
        const int kvbase = kb * 32;
        __syncthreads();
#pragma unroll
        for (int it = 0; it < 2; it++) {
            int id = tid + it * 256;   // 0..511 float4s
            int r = id >> 4, c4 = id & 15;
            float4 kv = *reinterpret_cast<const float4*>(&g_k[gbase + (long)(kvbase + r) * HD + c4 * 4]);
            *reinterpret_cast<float4*>(&Ks[r][c4 * 4]) = kv;
            float4 vv = *reinterpret_cast<const float4*>(&g_v[gbase + (long)(kvbase + r) * HD + c4 * 4]);
            *reinterpret_cast<float4*>(&Vs[r][c4 * 4]) = vv;
        }
        if (tid < 32) amks[tid] = am[b * SEQ + kvbase + tid];
        __syncthreads();

        // S = Q K^T  (4 rows x 2 cols per thread)
        float s[4][2] = {{0,0},{0,0},{0,0},{0,0}};
#pragma unroll 4
        for (int d = 0; d < 64; d += 4) {
            float4 qv[4], kv4[2];
#pragma unroll
            for (int i = 0; i < 4; i++)
                qv[i] = *reinterpret_cast<const float4*>(&Qs[r0 + i][d]);
#pragma unroll
            for (int j = 0; j < 2; j++)
                kv4[j] = *reinterpret_cast<const float4*>(&Ks[c0 + j][d]);
#pragma unroll
            for (int i = 0; i < 4; i++)
#pragma unroll
                for (int j = 0; j < 2; j++)
                    s[i][j] += qv[i].x * kv4[j].x + qv[i].y * kv4[j].y
                             + qv[i].z * kv4[j].z + qv[i].w * kv4[j].w;
        }

        // mask + online softmax (row stats held redundantly in the 16 lanes of a row)
#pragma unroll
        for (int i = 0; i < 4; i++) {
            const int qidx = qbase + r0 + i;
            float sv[2];
            float rm = -CUDART_INF_F;
#pragma unroll
            for (int j = 0; j < 2; j++) {
                int kidx = kvbase + c0 + j;
                float fm = (kidx > qidx) ? 1.0f : 0.0f;
                float pm = 1.0f - amq[i] * amks[c0 + j];
                float mv = fmaxf(fm, pm);
                float val = (s[i][j] + (-3.402823466e38f) * mv) * 0.03125f;
                sv[j] = val;
                rm = fmaxf(rm, val);
            }
#pragma unroll
            for (int off = 8; off >= 1; off >>= 1)
                rm = fmaxf(rm, __shfl_xor_sync(0xffffffffu, rm, off));
            float mn  = fmaxf(m_i[i], rm);
            float fct = __expf(m_i[i] - mn);
            float p0  = __expf(sv[0] - mn);
            float p1  = __expf(sv[1] - mn);
            float rs  = p0 + p1;
#pragma unroll
            for (int off = 8; off >= 1; off >>= 1)
                rs += __shfl_xor_sync(0xffffffffu, rs, off);
            l_i[i] = l_i[i] * fct + rs;
            m_i[i] = mn;
#pragma unroll
            for (int j = 0; j < 4; j++) o[i][j] *= fct;
            Ps[r0 + i][c0 + 0] = p0;
            Ps[r0 + i][c0 + 1] = p1;
        }
        __syncthreads();

        // O += P V  (4 rows x 4 cols per thread)
#pragma unroll 8
        for (int c = 0; c < 32; c++) {
            float4 vv = *reinterpret_cast<const float4*>(&Vs[c][n0]);
#pragma unroll
            for (int i = 0; i < 4; i++) {
                float p = Ps[r0 + i][c];
                o[i][0] += p * vv.x;
                o[i][1] += p * vv.y;
                o[i][2] += p * vv.z;
                o[i][3] += p * vv.w;
            }
        }
    }

    // normalize + write ctx (layout [b, l, h*64+d])
#pragma unroll
    for (int i = 0; i < 4; i++) {
        float inv = 1.0f / l_i[i];
        float4 v = make_float4(o[i][0] * inv, o[i][1] * inv, o[i][2] * inv, o[i][3] * inv);
        *reinterpret_cast<float4*>(&g_ctx[gbase + (long)(qbase + r0 + i) * HD + n0]) = v;
    }
}

// ---------------------------------------------------------------------------
extern "C" void kernel_launch(void* const* d_in, const int* in_sizes, int n_in,
                              void* d_out, int out_size)
{
    const float* input = (const float*)d_in[0];
    const float* amask = (const float*)d_in[1];
    const float* wq    = (const float*)d_in[2];
    const float* wk    = (const float*)d_in[3];
    const float* wv    = (const float*)d_in[4];
    const float* wo    = (const float*)d_in[5];
    float* out = (float*)d_out;

    dim3 gq(HD / 128, ROWS / 128, 3);     // (8, 32, 3)
    qkv_gemm_kernel<<<gq, 256>>>(input, wq, wk, wv);

    dim3 gf(SEQ / 64, NHEADS, NB);        // (32, 16, 2)
    flash_kernel<<<gf, 256>>>(amask);

    dim3 go(HD / 128, ROWS / 128);        // (8, 32)
    out_gemm_kernel<<<go, 256>>>(wo, out);
}

// round 3
// speedup vs baseline: 1.5098x; 1.5098x over previous
#include <cuda_runtime.h>
#include <math_constants.h>
#include <cstdint>

#define HD     1024
#define NHEADS 16
#define DHEAD  64
#define SEQ    2048
#define NB     2
#define ROWS   (NB * SEQ)   // 4096

// Scratch (allocation-free rule: __device__ globals)
__device__ float g_q[ROWS * HD];
__device__ float g_k[ROWS * HD];
__device__ float g_v[ROWS * HD];
__device__ float g_ctx[ROWS * HD];

// ---------------------------------------------------------------------------
// Helpers
// ---------------------------------------------------------------------------
__device__ __forceinline__ uint32_t cvt_tf32(float x) {
    uint32_t u;
    asm("cvt.rna.tf32.f32 %0, %1;" : "=r"(u) : "f"(x));
    return u;
}
__device__ __forceinline__ void cp16(void* dst, const void* src) {
    uint32_t d = (uint32_t)__cvta_generic_to_shared(dst);
    asm volatile("cp.async.cg.shared.global [%0], [%1], 16;" :: "r"(d), "l"(src));
}
#define CP_COMMIT()  asm volatile("cp.async.commit_group;" ::: "memory")
#define CP_WAIT(n)   asm volatile("cp.async.wait_group %0;" :: "n"(n) : "memory")

__device__ __forceinline__ void mma_tf32(float* d, const uint32_t* a, const uint32_t* b) {
    asm volatile("mma.sync.aligned.m16n8k8.row.col.f32.tf32.tf32.f32 "
                 "{%0,%1,%2,%3}, {%4,%5,%6,%7}, {%8,%9}, {%0,%1,%2,%3};"
                 : "+f"(d[0]), "+f"(d[1]), "+f"(d[2]), "+f"(d[3])
                 : "r"(a[0]), "r"(a[1]), "r"(a[2]), "r"(a[3]),
                   "r"(b[0]), "r"(b[1]));
}

// ---------------------------------------------------------------------------
// tf32 tensor-core GEMM: C[M,N] = A[M,K] @ B[K,N], all row-major fp32.
// CTA tile 128x128, 8 warps (4m x 2n), warp tile 32x64, K staged by 16,
// cp.async double-buffered. Fragments rounded to tf32 with RNA in registers.
// ---------------------------------------------------------------------------
struct GemmSmem {
    float As[2][128][20];   // [buf][m][k]  pad 20 -> conflict-free frag loads
    float Bs[2][16][132];   // [buf][k][n]  pad 132 -> conflict-free frag loads
};

__device__ __forceinline__ void gemm_stage_load(const float* __restrict__ A,
                                                const float* __restrict__ B,
                                                GemmSmem* sm, int buf,
                                                int bm, int bn, int k0, int tid)
{
#pragma unroll
    for (int i = 0; i < 2; i++) {
        int c = tid + i * 256;              // 0..511
        int ar = c >> 2, ac = c & 3;        // A: 128 rows x 4 chunks
        cp16(&sm->As[buf][ar][ac * 4], &A[(size_t)(bm + ar) * HD + k0 + ac * 4]);
        int br = c >> 5, bc = c & 31;       // B: 16 rows x 32 chunks
        cp16(&sm->Bs[buf][br][bc * 4], &B[(size_t)(k0 + br) * HD + bn + bc * 4]);
    }
}

__device__ __forceinline__ void gemm_tf32_body(const float* __restrict__ A,
                                               const float* __restrict__ B,
                                               float* __restrict__ C)
{
    __shared__ GemmSmem sm;

    const int tid  = threadIdx.x;
    const int lane = tid & 31;
    const int warp = tid >> 5;
    const int wm   = warp >> 1;          // 0..3
    const int wn   = warp & 1;           // 0..1
    const int m0   = wm * 32;
    const int n0   = wn * 64;
    const int gr   = lane >> 2;          // 0..7
    const int tg   = lane & 3;           // 0..3
    const int bm   = blockIdx.y << 7;
    const int bn   = blockIdx.x << 7;

    float acc[2][8][4];
#pragma unroll
    for (int mi = 0; mi < 2; mi++)
#pragma unroll
        for (int ni = 0; ni < 8; ni++)
#pragma unroll
            for (int j = 0; j < 4; j++) acc[mi][ni][j] = 0.0f;

    gemm_stage_load(A, B, &sm, 0, bm, bn, 0, tid);
    CP_COMMIT();

    for (int s = 0; s < 64; s++) {
        const int buf = s & 1;
        if (s < 63) {
            gemm_stage_load(A, B, &sm, buf ^ 1, bm, bn, (s + 1) << 4, tid);
            CP_COMMIT();
            CP_WAIT(1);
        } else {
            CP_WAIT(0);
        }
        __syncthreads();

#pragma unroll
        for (int kk = 0; kk < 16; kk += 8) {
            uint32_t a[2][4], b[8][2];
#pragma unroll
            for (int mi = 0; mi < 2; mi++) {
                int r = m0 + mi * 16 + gr;
                a[mi][0] = cvt_tf32(sm.As[buf][r][kk + tg]);
                a[mi][1] = cvt_tf32(sm.As[buf][r + 8][kk + tg]);
                a[mi][2] = cvt_tf32(sm.As[buf][r][kk + tg + 4]);
                a[mi][3] = cvt_tf32(sm.As[buf][r + 8][kk + tg + 4]);
            }
#pragma unroll
            for (int ni = 0; ni < 8; ni++) {
                int cc = n0 + ni * 8 + gr;
                b[ni][0] = cvt_tf32(sm.Bs[buf][kk + tg][cc]);
                b[ni][1] = cvt_tf32(sm.Bs[buf][kk + tg + 4][cc]);
            }
#pragma unroll
            for (int mi = 0; mi < 2; mi++)
#pragma unroll
                for (int ni = 0; ni < 8; ni++)
                    mma_tf32(acc[mi][ni], a[mi], b[ni]);
        }
        __syncthreads();
    }

    // Epilogue
#pragma unroll
    for (int mi = 0; mi < 2; mi++) {
#pragma unroll
        for (int ni = 0; ni < 8; ni++) {
            int r  = bm + m0 + mi * 16 + gr;
            int cc = bn + n0 + ni * 8 + 2 * tg;
            float2 v0 = make_float2(acc[mi][ni][0], acc[mi][ni][1]);
            float2 v1 = make_float2(acc[mi][ni][2], acc[mi][ni][3]);
            *reinterpret_cast<float2*>(&C[(size_t)r * HD + cc]) = v0;
            *reinterpret_cast<float2*>(&C[(size_t)(r + 8) * HD + cc]) = v1;
        }
    }
}

__global__ __launch_bounds__(256, 2)
void qkv_gemm_kernel(const float* __restrict__ X,
                     const float* __restrict__ Wq,
                     const float* __restrict__ Wk,
                     const float* __restrict__ Wv)
{
    const int z = blockIdx.z;
    const float* W = (z == 0) ? Wq : (z == 1) ? Wk : Wv;
    float* O = (z == 0) ? g_q : (z == 1) ? g_k : g_v;
    gemm_tf32_body(X, W, O);
}

__global__ __launch_bounds__(256, 2)
void out_gemm_kernel(const float* __restrict__ Wo, float* __restrict__ Out)
{
    gemm_tf32_body(g_ctx, Wo, Out);
}

// ---------------------------------------------------------------------------
// Flash attention, fp32 (unchanged from passing R1 kernel).
// ---------------------------------------------------------------------------
__global__ __launch_bounds__(256)
void flash_kernel(const float* __restrict__ am)
{
    __shared__ float Qs[64][68];
    __shared__ float Ks[32][68];
    __shared__ float Vs[32][68];
    __shared__ float Ps[64][33];
    __shared__ float amks[32];

    const int tid = threadIdx.x;
    const int tr = tid >> 4;
    const int tc = tid & 15;
    const int r0 = tr * 4;
    const int c0 = tc * 2;
    const int n0 = tc * 4;

    const int qb = blockIdx.x;
    const int h  = blockIdx.y;
    const int b  = blockIdx.z;
    const int qbase = qb * 64;

    const long gbase = (long)b * SEQ * HD + h * DHEAD;

#pragma unroll
    for (int it = 0; it < 4; it++) {
        int id = tid + it * 256;
        int r = id >> 4, c4 = id & 15;
        float4 v = *reinterpret_cast<const float4*>(&g_q[gbase + (long)(qbase + r) * HD + c4 * 4]);
        *reinterpret_cast<float4*>(&Qs[r][c4 * 4]) = v;
    }

    float amq[4];
#pragma unroll
    for (int i = 0; i < 4; i++)
        amq[i] = am[b * SEQ + qbase + r0 + i];

    float m_i[4], l_i[4], o[4][4];
#pragma unroll
    for (int i = 0; i < 4; i++) {
        m_i[i] = -CUDART_INF_F;
        l_i[i] = 0.0f;
#pragma unroll
        for (int j = 0; j < 4; j++) o[i][j] = 0.0f;
    }

    const int nkb = qb * 2 + 2;
    for (int kb = 0; kb < nkb; kb++) {
        const int kvbase = kb * 32;
        __syncthreads();
#pragma unroll
        for (int it = 0; it < 2; it++) {
            int id = tid + it * 256;
            int r = id >> 4, c4 = id & 15;
            float4 kv = *reinterpret_cast<const float4*>(&g_k[gbase + (long)(kvbase + r) * HD + c4 * 4]);
            *reinterpret_cast<float4*>(&Ks[r][c4 * 4]) = kv;
            float4 vv = *reinterpret_cast<const float4*>(&g_v[gbase + (long)(kvbase + r) * HD + c4 * 4]);
            *reinterpret_cast<float4*>(&Vs[r][c4 * 4]) = vv;
        }
        if (tid < 32) amks[tid] = am[b * SEQ + kvbase + tid];
        __syncthreads();

        float s[4][2] = {{0,0},{0,0},{0,0},{0,0}};
#pragma unroll 4
        for (int d = 0; d < 64; d += 4) {
            float4 qv[4], kv4[2];
#pragma unroll
            for (int i = 0; i < 4; i++)
                qv[i] = *reinterpret_cast<const float4*>(&Qs[r0 + i][d]);
#pragma unroll
            for (int j = 0; j < 2; j++)
                kv4[j] = *reinterpret_cast<const float4*>(&Ks[c0 + j][d]);
#pragma unroll
            for (int i = 0; i < 4; i++)
#pragma unroll
                for (int j = 0; j < 2; j++)
                    s[i][j] += qv[i].x * kv4[j].x + qv[i].y * kv4[j].y
                             + qv[i].z * kv4[j].z + qv[i].w * kv4[j].w;
        }

#pragma unroll
        for (int i = 0; i < 4; i++) {
            const int qidx = qbase + r0 + i;
            float sv[2];
            float rm = -CUDART_INF_F;
#pragma unroll
            for (int j = 0; j < 2; j++) {
                int kidx = kvbase + c0 + j;
                float fm = (kidx > qidx) ? 1.0f : 0.0f;
                float pm = 1.0f - amq[i] * amks[c0 + j];
                float mv = fmaxf(fm, pm);
                float val = (s[i][j] + (-3.402823466e38f) * mv) * 0.03125f;
                sv[j] = val;
                rm = fmaxf(rm, val);
            }
#pragma unroll
            for (int off = 8; off >= 1; off >>= 1)
                rm = fmaxf(rm, __shfl_xor_sync(0xffffffffu, rm, off));
            float mn  = fmaxf(m_i[i], rm);
            float fct = __expf(m_i[i] - mn);
            float p0  = __expf(sv[0] - mn);
            float p1  = __expf(sv[1] - mn);
            float rs  = p0 + p1;
#pragma unroll
            for (int off = 8; off >= 1; off >>= 1)
                rs += __shfl_xor_sync(0xffffffffu, rs, off);
            l_i[i] = l_i[i] * fct + rs;
            m_i[i] = mn;
#pragma unroll
            for (int j = 0; j < 4; j++) o[i][j] *= fct;
            Ps[r0 + i][c0 + 0] = p0;
            Ps[r0 + i][c0 + 1] = p1;
        }
        __syncthreads();

#pragma unroll 8
        for (int c = 0; c < 32; c++) {
            float4 vv = *reinterpret_cast<const float4*>(&Vs[c][n0]);
#pragma unroll
            for (int i = 0; i < 4; i++) {
                float p = Ps[r0 + i][c];
                o[i][0] += p * vv.x;
                o[i][1] += p * vv.y;
                o[i][2] += p * vv.z;
                o[i][3] += p * vv.w;
            }
        }
    }

#pragma unroll
    for (int i = 0; i < 4; i++) {
        float inv = 1.0f / l_i[i];
        float4 v = make_float4(o[i][0] * inv, o[i][1] * inv, o[i][2] * inv, o[i][3] * inv);
        *reinterpret_cast<float4*>(&g_ctx[gbase + (long)(qbase + r0 + i) * HD + n0]) = v;
    }
}

// ---------------------------------------------------------------------------
extern "C" void kernel_launch(void* const* d_in, const int* in_sizes, int n_in,
                              void* d_out, int out_size)
{
    const float* input = (const float*)d_in[0];
    const float* amask = (const float*)d_in[1];
    const float* wq    = (const float*)d_in[2];
    const float* wk    = (const float*)d_in[3];
    const float* wv    = (const float*)d_in[4];
    const float* wo    = (const float*)d_in[5];
    float* out = (float*)d_out;

    dim3 gq(HD / 128, ROWS / 128, 3);     // (8, 32, 3)
    qkv_gemm_kernel<<<gq, 256>>>(input, wq, wk, wv);

    dim3 gf(SEQ / 64, NHEADS, NB);        // (32, 16, 2)
    flash_kernel<<<gf, 256>>>(amask);

    dim3 go(HD / 128, ROWS / 128);        // (8, 32)
    out_gemm_kernel<<<go, 256>>>(wo, out);
}

// round 5
// speedup vs baseline: 3.3738x; 2.2346x over previous
#include <cuda_runtime.h>
#include <math_constants.h>
#include <cstdint>

#define HD     1024
#define NHEADS 16
#define DHEAD  64
#define SEQ    2048
#define NB     2
#define ROWS   (NB * SEQ)   // 4096

// Scratch (allocation-free rule: __device__ globals)
__device__ float g_q[ROWS * HD];
__device__ float g_k[ROWS * HD];
__device__ float g_v[ROWS * HD];
__device__ float g_ctx[ROWS * HD];

// ---------------------------------------------------------------------------
// Helpers
// ---------------------------------------------------------------------------
__device__ __forceinline__ uint32_t cvt_tf32(float x) {
    uint32_t u;
    asm("cvt.rna.tf32.f32 %0, %1;" : "=r"(u) : "f"(x));
    return u;
}
__device__ __forceinline__ float rnd_tf32(float x) {
    return __uint_as_float(cvt_tf32(x));
}
__device__ __forceinline__ void cp16(void* dst, const void* src) {
    uint32_t d = (uint32_t)__cvta_generic_to_shared(dst);
    asm volatile("cp.async.cg.shared.global [%0], [%1], 16;" :: "r"(d), "l"(src));
}
#define CP_COMMIT()  asm volatile("cp.async.commit_group;" ::: "memory")
#define CP_WAIT(n)   asm volatile("cp.async.wait_group %0;" :: "n"(n) : "memory")

__device__ __forceinline__ void mma_tf32(float* d, const uint32_t* a, const uint32_t* b) {
    asm volatile("mma.sync.aligned.m16n8k8.row.col.f32.tf32.tf32.f32 "
                 "{%0,%1,%2,%3}, {%4,%5,%6,%7}, {%8,%9}, {%0,%1,%2,%3};"
                 : "+f"(d[0]), "+f"(d[1]), "+f"(d[2]), "+f"(d[3])
                 : "r"(a[0]), "r"(a[1]), "r"(a[2]), "r"(a[3]),
                   "r"(b[0]), "r"(b[1]));
}

// ---------------------------------------------------------------------------
// tf32 tensor-core GEMM: C[M,N] = A[M,K] @ B[K,N], all row-major fp32.
// CTA tile 128x128, 8 warps (4m x 2n), warp tile 32x64, K staged by 16,
// cp.async double-buffered. Fragments rounded to tf32 with RNA in registers.
// ---------------------------------------------------------------------------
struct GemmSmem {
    float As[2][128][20];
    float Bs[2][16][132];
};

__device__ __forceinline__ void gemm_stage_load(const float* __restrict__ A,
                                                const float* __restrict__ B,
                                                GemmSmem* sm, int buf,
                                                int bm, int bn, int k0, int tid)
{
#pragma unroll
    for (int i = 0; i < 2; i++) {
        int c = tid + i * 256;
        int ar = c >> 2, ac = c & 3;
        cp16(&sm->As[buf][ar][ac * 4], &A[(size_t)(bm + ar) * HD + k0 + ac * 4]);
        int br = c >> 5, bc = c & 31;
        cp16(&sm->Bs[buf][br][bc * 4], &B[(size_t)(k0 + br) * HD + bn + bc * 4]);
    }
}

__device__ __forceinline__ void gemm_tf32_body(const float* __restrict__ A,
                                               const float* __restrict__ B,
                                               float* __restrict__ C)
{
    __shared__ GemmSmem sm;

    const int tid  = threadIdx.x;
    const int lane = tid & 31;
    const int warp = tid >> 5;
    const int wm   = warp >> 1;
    const int wn   = warp & 1;
    const int m0   = wm * 32;
    const int n0   = wn * 64;
    const int gr   = lane >> 2;
    const int tg   = lane & 3;
    const int bm   = blockIdx.y << 7;
    const int bn   = blockIdx.x << 7;

    float acc[2][8][4];
#pragma unroll
    for (int mi = 0; mi < 2; mi++)
#pragma unroll
        for (int ni = 0; ni < 8; ni++)
#pragma unroll
            for (int j = 0; j < 4; j++) acc[mi][ni][j] = 0.0f;

    gemm_stage_load(A, B, &sm, 0, bm, bn, 0, tid);
    CP_COMMIT();

    for (int s = 0; s < 64; s++) {
        const int buf = s & 1;
        if (s < 63) {
            gemm_stage_load(A, B, &sm, buf ^ 1, bm, bn, (s + 1) << 4, tid);
            CP_COMMIT();
            CP_WAIT(1);
        } else {
            CP_WAIT(0);
        }
        __syncthreads();

#pragma unroll
        for (int kk = 0; kk < 16; kk += 8) {
            uint32_t a[2][4], b[8][2];
#pragma unroll
            for (int mi = 0; mi < 2; mi++) {
                int r = m0 + mi * 16 + gr;
                a[mi][0] = cvt_tf32(sm.As[buf][r][kk + tg]);
                a[mi][1] = cvt_tf32(sm.As[buf][r + 8][kk + tg]);
                a[mi][2] = cvt_tf32(sm.As[buf][r][kk + tg + 4]);
                a[mi][3] = cvt_tf32(sm.As[buf][r + 8][kk + tg + 4]);
            }
#pragma unroll
            for (int ni = 0; ni < 8; ni++) {
                int cc = n0 + ni * 8 + gr;
                b[ni][0] = cvt_tf32(sm.Bs[buf][kk + tg][cc]);
                b[ni][1] = cvt_tf32(sm.Bs[buf][kk + tg + 4][cc]);
            }
#pragma unroll
            for (int mi = 0; mi < 2; mi++)
#pragma unroll
                for (int ni = 0; ni < 8; ni++)
                    mma_tf32(acc[mi][ni], a[mi], b[ni]);
        }
        __syncthreads();
    }

#pragma unroll
    for (int mi = 0; mi < 2; mi++) {
#pragma unroll
        for (int ni = 0; ni < 8; ni++) {
            int r  = bm + m0 + mi * 16 + gr;
            int cc = bn + n0 + ni * 8 + 2 * tg;
            float2 v0 = make_float2(acc[mi][ni][0], acc[mi][ni][1]);
            float2 v1 = make_float2(acc[mi][ni][2], acc[mi][ni][3]);
            *reinterpret_cast<float2*>(&C[(size_t)r * HD + cc]) = v0;
            *reinterpret_cast<float2*>(&C[(size_t)(r + 8) * HD + cc]) = v1;
        }
    }
}

__global__ __launch_bounds__(256, 2)
void qkv_gemm_kernel(const float* __restrict__ X,
                     const float* __restrict__ Wq,
                     const float* __restrict__ Wk,
                     const float* __restrict__ Wv)
{
    const int z = blockIdx.z;
    const float* W = (z == 0) ? Wq : (z == 1) ? Wk : Wv;
    float* O = (z == 0) ? g_q : (z == 1) ? g_k : g_v;
    gemm_tf32_body(X, W, O);
}

__global__ __launch_bounds__(256, 2)
void out_gemm_kernel(const float* __restrict__ Wo, float* __restrict__ Out)
{
    gemm_tf32_body(g_ctx, Wo, Out);
}

// ---------------------------------------------------------------------------
// Tensor-core flash attention (tf32 mma.sync). BQ=64, BKV=64, d=64.
// 4 warps; warp w owns query rows [w*16, w*16+16). Full softmax row in-warp.
// QP buffer: holds Q during fragment preload, then reused for P (rows are
// warp-private, so no cross-warp hazard).
// Pads: stride 68 floats (≡4 mod 32) for QP/K A/B-frag reads;
//       stride 72 floats (≡8 mod 32) for V transposed B-frag reads.
// ---------------------------------------------------------------------------
struct FlashSmem {
    float QP[64][68];
    float K[64][68];
    float V[64][72];
    float amk[64];
};
#define FLASH_SMEM ((int)sizeof(FlashSmem))

__global__ __launch_bounds__(128)
void flash_tc_kernel(const float* __restrict__ am)
{
    extern __shared__ char smem_raw[];
    FlashSmem& sm = *reinterpret_cast<FlashSmem*>(smem_raw);

    const int tid  = threadIdx.x;
    const int lane = tid & 31;
    const int warp = tid >> 5;
    const int gr   = lane >> 2;
    const int tg   = lane & 3;
    const int m0   = warp * 16;

    const int qb = blockIdx.x;
    const int h  = blockIdx.y;
    const int b  = blockIdx.z;
    const int qbase = qb * 64;
    const size_t gbase = (size_t)b * SEQ * HD + h * DHEAD;

    // Stage Q (tf32-rounded)
#pragma unroll
    for (int it = 0; it < 8; ++it) {
        int id = tid + it * 128;
        int r = id >> 4, c4 = id & 15;
        float4 v = *reinterpret_cast<const float4*>(&g_q[gbase + (size_t)(qbase + r) * HD + c4 * 4]);
        v.x = rnd_tf32(v.x); v.y = rnd_tf32(v.y);
        v.z = rnd_tf32(v.z); v.w = rnd_tf32(v.w);
        *reinterpret_cast<float4*>(&sm.QP[r][c4 * 4]) = v;
    }
    const float amq0 = am[b * SEQ + qbase + m0 + gr];
    const float amq1 = am[b * SEQ + qbase + m0 + 8 + gr];
    __syncthreads();

    // Preload Q fragments (warp-private rows)
    uint32_t aQ[8][4];
#pragma unroll
    for (int kt = 0; kt < 8; ++kt) {
        aQ[kt][0] = __float_as_uint(sm.QP[m0 + gr][kt * 8 + tg]);
        aQ[kt][1] = __float_as_uint(sm.QP[m0 + gr + 8][kt * 8 + tg]);
        aQ[kt][2] = __float_as_uint(sm.QP[m0 + gr][kt * 8 + tg + 4]);
        aQ[kt][3] = __float_as_uint(sm.QP[m0 + gr + 8][kt * 8 + tg + 4]);
    }

    float m0_i = -CUDART_INF_F, m1_i = -CUDART_INF_F;
    float l0 = 0.0f, l1 = 0.0f;
    float o[8][4];
#pragma unroll
    for (int nt = 0; nt < 8; ++nt)
#pragma unroll
        for (int j = 0; j < 4; ++j) o[nt][j] = 0.0f;

    const float MASKC = -3.402823466e38f;
    const int row0 = qbase + m0 + gr;
    const int row1 = row0 + 8;

    for (int kb = 0; kb <= qb; ++kb) {
        const int kvbase = kb * 64;
        __syncthreads();
        // Stage K, V (tf32-rounded)
#pragma unroll
        for (int it = 0; it < 8; ++it) {
            int id = tid + it * 128;
            int r = id >> 4, c4 = id & 15;
            float4 kv = *reinterpret_cast<const float4*>(&g_k[gbase + (size_t)(kvbase + r) * HD + c4 * 4]);
            kv.x = rnd_tf32(kv.x); kv.y = rnd_tf32(kv.y);
            kv.z = rnd_tf32(kv.z); kv.w = rnd_tf32(kv.w);
            *reinterpret_cast<float4*>(&sm.K[r][c4 * 4]) = kv;
            float4 vv = *reinterpret_cast<const float4*>(&g_v[gbase + (size_t)(kvbase + r) * HD + c4 * 4]);
            vv.x = rnd_tf32(vv.x); vv.y = rnd_tf32(vv.y);
            vv.z = rnd_tf32(vv.z); vv.w = rnd_tf32(vv.w);
            *reinterpret_cast<float4*>(&sm.V[r][c4 * 4]) = vv;
        }
        if (tid < 64) sm.amk[tid] = am[b * SEQ + kvbase + tid];
        __syncthreads();

        // S = Q K^T  (warp computes m16 x n64)
        float s[8][4];
#pragma unroll
        for (int nt = 0; nt < 8; ++nt) {
#pragma unroll
            for (int j = 0; j < 4; ++j) s[nt][j] = 0.0f;
#pragma unroll
            for (int kt = 0; kt < 8; ++kt) {
                uint32_t bk[2];
                bk[0] = __float_as_uint(sm.K[nt * 8 + gr][kt * 8 + tg]);
                bk[1] = __float_as_uint(sm.K[nt * 8 + gr][kt * 8 + tg + 4]);
                mma_tf32(s[nt], aQ[kt], bk);
            }
        }

        // Mask (faithful) + row max
        float mx0 = -CUDART_INF_F, mx1 = -CUDART_INF_F;
#pragma unroll
        for (int nt = 0; nt < 8; ++nt) {
            const int col = kvbase + nt * 8 + 2 * tg;
            const float ak0 = sm.amk[nt * 8 + 2 * tg];
            const float ak1 = sm.amk[nt * 8 + 2 * tg + 1];
            float mv;
            mv = fmaxf((col     > row0) ? 1.0f : 0.0f, 1.0f - amq0 * ak0);
            s[nt][0] = (s[nt][0] + MASKC * mv) * 0.03125f;
            mv = fmaxf((col + 1 > row0) ? 1.0f : 0.0f, 1.0f - amq0 * ak1);
            s[nt][1] = (s[nt][1] + MASKC * mv) * 0.03125f;
            mv = fmaxf((col     > row1) ? 1.0f : 0.0f, 1.0f - amq1 * ak0);
            s[nt][2] = (s[nt][2] + MASKC * mv) * 0.03125f;
            mv = fmaxf((col + 1 > row1) ? 1.0f : 0.0f, 1.0f - amq1 * ak1);
            s[nt][3] = (s[nt][3] + MASKC * mv) * 0.03125f;
            mx0 = fmaxf(mx0, fmaxf(s[nt][0], s[nt][1]));
            mx1 = fmaxf(mx1, fmaxf(s[nt][2], s[nt][3]));
        }
        mx0 = fmaxf(mx0, __shfl_xor_sync(0xffffffffu, mx0, 1));
        mx0 = fmaxf(mx0, __shfl_xor_sync(0xffffffffu, mx0, 2));
        mx1 = fmaxf(mx1, __shfl_xor_sync(0xffffffffu, mx1, 1));
        mx1 = fmaxf(mx1, __shfl_xor_sync(0xffffffffu, mx1, 2));

        const float mn0 = fmaxf(m0_i, mx0);
        const float mn1 = fmaxf(m1_i, mx1);
        const float f0 = __expf(m0_i - mn0);
        const float f1 = __expf(m1_i - mn1);

        float rs0 = 0.0f, rs1 = 0.0f;
#pragma unroll
        for (int nt = 0; nt < 8; ++nt) {
            float p00 = __expf(s[nt][0] - mn0);
            float p01 = __expf(s[nt][1] - mn0);
            float p10 = __expf(s[nt][2] - mn1);
            float p11 = __expf(s[nt][3] - mn1);
            rs0 += p00 + p01;
            rs1 += p10 + p11;
            float2 w0 = make_float2(rnd_tf32(p00), rnd_tf32(p01));
            float2 w1 = make_float2(rnd_tf32(p10), rnd_tf32(p11));
            *reinterpret_cast<float2*>(&sm.QP[m0 + gr][nt * 8 + 2 * tg]) = w0;
            *reinterpret_cast<float2*>(&sm.QP[m0 + gr + 8][nt * 8 + 2 * tg]) = w1;
        }
        rs0 += __shfl_xor_sync(0xffffffffu, rs0, 1);
        rs0 += __shfl_xor_sync(0xffffffffu, rs0, 2);
        rs1 += __shfl_xor_sync(0xffffffffu, rs1, 1);
        rs1 += __shfl_xor_sync(0xffffffffu, rs1, 2);

        l0 = l0 * f0 + rs0;
        l1 = l1 * f1 + rs1;
        m0_i = mn0;
        m1_i = mn1;
#pragma unroll
        for (int nt = 0; nt < 8; ++nt) {
            o[nt][0] *= f0;  o[nt][1] *= f0;
            o[nt][2] *= f1;  o[nt][3] *= f1;
        }
        __syncwarp();

        // O += P V
#pragma unroll
        for (int kt = 0; kt < 8; ++kt) {
            uint32_t aP[4];
            aP[0] = __float_as_uint(sm.QP[m0 + gr][kt * 8 + tg]);
            aP[1] = __float_as_uint(sm.QP[m0 + gr + 8][kt * 8 + tg]);
            aP[2] = __float_as_uint(sm.QP[m0 + gr][kt * 8 + tg + 4]);
            aP[3] = __float_as_uint(sm.QP[m0 + gr + 8][kt * 8 + tg + 4]);
#pragma unroll
            for (int nt = 0; nt < 8; ++nt) {
                uint32_t bv[2];
                bv[0] = __float_as_uint(sm.V[kt * 8 + tg][nt * 8 + gr]);
                bv[1] = __float_as_uint(sm.V[kt * 8 + tg + 4][nt * 8 + gr]);
                mma_tf32(o[nt], aP, bv);
            }
        }
        __syncwarp();
    }

    // Epilogue: normalize + write ctx
    const float inv0 = 1.0f / l0;
    const float inv1 = 1.0f / l1;
#pragma unroll
    for (int nt = 0; nt < 8; ++nt) {
        const int cc = nt * 8 + 2 * tg;
        float2 v0 = make_float2(o[nt][0] * inv0, o[nt][1] * inv0);
        float2 v1 = make_float2(o[nt][2] * inv1, o[nt][3] * inv1);
        *reinterpret_cast<float2*>(&g_ctx[gbase + (size_t)row0 * HD + cc]) = v0;
        *reinterpret_cast<float2*>(&g_ctx[gbase + (size_t)row1 * HD + cc]) = v1;
    }
}

// ---------------------------------------------------------------------------
extern "C" void kernel_launch(void* const* d_in, const int* in_sizes, int n_in,
                              void* d_out, int out_size)
{
    const float* input = (const float*)d_in[0];
    const float* amask = (const float*)d_in[1];
    const float* wq    = (const float*)d_in[2];
    const float* wk    = (const float*)d_in[3];
    const float* wv    = (const float*)d_in[4];
    const float* wo    = (const float*)d_in[5];
    float* out = (float*)d_out;

    cudaFuncSetAttribute(flash_tc_kernel,
                         cudaFuncAttributeMaxDynamicSharedMemorySize, FLASH_SMEM);

    dim3 gq(HD / 128, ROWS / 128, 3);     // (8, 32, 3)
    qkv_gemm_kernel<<<gq, 256>>>(input, wq, wk, wv);

    dim3 gf(SEQ / 64, NHEADS, NB);        // (32, 16, 2)
    flash_tc_kernel<<<gf, 128, FLASH_SMEM>>>(amask);

    dim3 go(HD / 128, ROWS / 128);        // (8, 32)
    out_gemm_kernel<<<go, 256>>>(wo, out);
}